// round 14
// baseline (speedup 1.0000x reference)
#include <cuda_runtime.h>
#include <cstdint>
#include <math.h>

#define Hdim 2048
#define Bdim 16
#define Tdim 1024
#define NIN 8
#define NOUT 8
#define TUNED 10
#define NCTA 128
#define RPC 16
#define NTH 256
#define KC 512
#define DTC 0.001f
#define BETAC 1.5f
#define PAD 32

typedef unsigned long long u64;

__device__ float g_Wm[Hdim * Hdim];
__device__ float g_v[2][2][8 * Hdim];        // [half][buf][b_local*Hdim + row]
__device__ float g_zt[Tdim * NCTA * 128];
__device__ float g_zp0[NCTA * 128];
__device__ unsigned g_wcnt[2][4 * PAD];      // [half][group*PAD]
__device__ unsigned g_zcnt[PAD];
__device__ int g_zflag;

__device__ __forceinline__ void cp16(float* d, const float* s) {
    unsigned ds = (unsigned)__cvta_generic_to_shared(d);
    asm volatile("cp.async.cg.shared.global [%0],[%1],16;" ::"r"(ds), "l"(s));
}
__device__ __forceinline__ unsigned ldrelax(const unsigned* p) {
    unsigned v;
    asm volatile("ld.relaxed.gpu.global.u32 %0,[%1];" : "=r"(v) : "l"(p));
    return v;
}
__device__ __forceinline__ unsigned ldacq(const unsigned* p) {
    unsigned v;
    asm volatile("ld.acquire.gpu.global.u32 %0,[%1];" : "=r"(v) : "l"(p));
    return v;
}
__device__ __forceinline__ void red_release(unsigned* p) {
    asm volatile("red.release.gpu.global.add.u32 [%0],1;" ::"l"(p) : "memory");
}
__device__ __forceinline__ void stcs(float* p, float v) {
    asm volatile("st.global.cs.f32 [%0],%1;" ::"l"(p), "f"(v));
}
__device__ __forceinline__ u64 fma2(u64 a, u64 b, u64 c) {
    u64 d;
    asm("fma.rn.f32x2 %0,%1,%2,%3;" : "=l"(d) : "l"(a), "l"(b), "l"(c));
    return d;
}
__device__ __forceinline__ float unpack_sum(u64 v) {
    float lo, hi;
    asm("mov.b64 {%0,%1},%2;" : "=f"(lo), "=f"(hi) : "l"(v));
    return lo + hi;
}
__device__ __forceinline__ float my_tanh(float x) {
    float e;
    asm("ex2.approx.f32 %0, %1;" : "=f"(e) : "f"(fabsf(x) * 2.8853900817779268f));
    float y = e + 1.0f;
    float r0;
    asm("rcp.approx.f32 %0, %1;" : "=f"(r0) : "f"(y));
    r0 = r0 * fmaf(-y, r0, 2.0f);
    float res = fmaf(-2.0f, r0, 1.0f);
    return copysignf(res, x);
}
__device__ __forceinline__ float merge32(float* a, int l) {
#pragma unroll
    for (int k = 0; k < 5; k++) {
        const int m = 1 << k;
        const bool s = (l >> k) & 1;
#pragma unroll
        for (int i = 0; i < (32 >> (k + 1)); i++) {
            float A = a[2 * i], B = a[2 * i + 1];
            float keep = s ? B : A;
            float send = s ? A : B;
            a[i] = keep + __shfl_xor_sync(0xffffffffu, send, m);
        }
    }
    return a[0];
}

__global__ void reset_counters() {
    int i = threadIdx.x;
    if (i < 4 * PAD) { g_wcnt[0][i] = 0u; g_wcnt[1][i] = 0u; }
    if (i < PAD) g_zcnt[i] = 0u;
    if (i == 0) g_zflag = 0;
}
__global__ void scan_wzh(const float* __restrict__ wzh) {
    int i = blockIdx.x * 256 + threadIdx.x;
    if (i < Hdim * NOUT && wzh[i] != 0.0f) g_zflag = 1;
}
__global__ void build_wm(const float* __restrict__ wt, const float* __restrict__ wf,
                         const float* __restrict__ mk) {
    int idx = blockIdx.x * 256 + threadIdx.x;
    if (idx < Hdim * Hdim) {
        int j = idx >> 11, k = idx & (Hdim - 1);
        float w = (k < TUNED) ? wt[j * TUNED + k] : wf[j * (Hdim - TUNED) + (k - TUNED)];
        g_Wm[idx] = mk[idx] * w;
    }
}
__global__ void zred(float* __restrict__ out_z) {
    int idx = blockIdx.x * 256 + threadIdx.x;
    int t = idx >> 7, bo = idx & 127;
    const float* p = g_zt + (size_t)t * (NCTA * 128) + bo;
    float s = 0.f;
#pragma unroll 8
    for (int c = 0; c < NCTA; c++) s += __ldcg(p + c * 128);
    out_z[((size_t)(bo >> 3) * Tdim + t) * NOUT + (bo & 7)] = s;
}

// prefetch chunk ci of a half's v: 8 batches x 512 floats = 16KB
__device__ __forceinline__ void pf_half(float* sV, const float* vsrc, int slot, int ci, int tid) {
    float* dst = sV + slot * 4096;
    const float* src = vsrc + ci * KC;
#pragma unroll
    for (int u = 0; u < 4; u++) {
        int seg = u * NTH + tid;          // 1024 segs of 16B
        int b = seg >> 7;                 // 128 segs per batch row
        int f = (seg & 127) << 2;
        cp16(dst + b * KC + f, src + (size_t)b * Hdim + f);
    }
    asm volatile("cp.async.commit_group;" ::: "memory");
}

// one chunk (512k) for one half: 8 rows x 8 batches, kg quarter, 128 fma2
__device__ __forceinline__ void cfma(const float* sWm, const float* sV, u64* acc,
                                     int rbase, int kg, int l, int ci, int slot) {
    const float* Wp = sWm + rbase * Hdim + ci * KC + kg * 128 + (l << 2);
    const float* Vp = sV + slot * 4096 + kg * 128 + (l << 2);
    ulonglong2 wv[8], vv[8];
#pragma unroll
    for (int rr = 0; rr < 8; rr++) wv[rr] = *(const ulonglong2*)(Wp + rr * Hdim);
#pragma unroll
    for (int q = 0; q < 8; q++) vv[q] = *(const ulonglong2*)(Vp + q * KC);
#pragma unroll
    for (int rr = 0; rr < 8; rr++)
#pragma unroll
        for (int q = 0; q < 8; q++) {
            u64 A = acc[rr * 8 + q];
            A = fma2(wv[rr].x, vv[q].x, A);
            A = fma2(wv[rr].y, vv[q].y, A);
            acc[rr * 8 + q] = A;
        }
}

__device__ __forceinline__ void wpoll(bool pre, const unsigned* p, unsigned tgt, int lane) {
    if (lane == 0 && !pre) {
        while (ldrelax(p) < tgt) {}
        while (ldacq(p) < tgt) {}
    }
    __syncwarp();
}

__global__ __launch_bounds__(NTH, 1) void rnn_persist(
    const float* __restrict__ x, const float* __restrict__ h0,
    const float* __restrict__ Wih, const float* __restrict__ Whz,
    const float* __restrict__ Wzh, const float* __restrict__ tau,
    float* __restrict__ out) {

    extern __shared__ float sm[];
    float* sWm  = sm;              // 32768
    float* sV   = sm + 32768;      // 16384 (4 slots x 4096)
    float* sHT0 = sm + 49152;      // 128 [row*8+b]
    float* sHT1 = sm + 49280;      // 128
    float* sZ   = sm + 49408;      // 128 (zf fallback)
    float* sX   = sm + 49536;      // 128 [b*8+i]
    float* sWi  = sm + 49664;      // 128
    float* sWz  = sm + 49792;      // 128
    float* sWo  = sm + 49920;      // 128 [o*16+j]
    float* sTa  = sm + 50048;      // 16
    float* sP   = sm + 50064;      // 512 [kg*128 + cell]

    const int tid = threadIdx.x;
    const int cta = blockIdx.x;
    const int l = tid & 31, w = tid >> 5;
    const int rg = w & 1, kg = w >> 1;           // 2 row-groups x 4 k-groups
    const int rbase = rg * 8;
    const int jrow = cta * RPC;
    const int myg = cta >> 5;
    const int zf = g_zflag;
    const int row = tid >> 3, q = tid & 7;       // owner cell (tid<128)

    float* out_h = out + (size_t)Bdim * Tdim * NOUT;
    float* out_r = out_h + (size_t)Bdim * Tdim * Hdim;

    const unsigned* pc0[4];
    const unsigned* pc1[4];
#pragma unroll
    for (int i = 0; i < 4; i++) {
        pc0[i] = &g_wcnt[0][((myg + i) & 3) * PAD];
        pc1[i] = &g_wcnt[1][((myg + i) & 3) * PAD];
    }
    const int ci0 = myg, ci1 = (myg + 1) & 3, ci2 = (myg + 2) & 3, ci3 = (myg + 3) & 3;

    // ---- one-time loads ----
    {
        const float4* src = (const float4*)(g_Wm + (size_t)jrow * Hdim);
        float4* dst = (float4*)sWm;
#pragma unroll 8
        for (int i = tid; i < RPC * Hdim / 4; i += NTH) dst[i] = src[i];
    }
    if (tid < 128) {
        int jj = tid >> 3, ii = tid & 7;
        sWi[tid] = Wih[(jrow + jj) * NIN + ii];
        sWz[tid] = Wzh[(jrow + jj) * NOUT + ii];
        int oo = tid >> 4, j2 = tid & 15;
        sWo[tid] = Whz[oo * Hdim + jrow + j2];
    }
    if (tid < RPC) sTa[tid] = tau[jrow + tid];
    __syncthreads();

    // ---- init state: tid<128 owns cell (row, q) of BOTH halves ----
    float h0r = 0.f, r0r = 1.f, hT0r = 0.f;
    float h1r = 0.f, r1r = 1.f, hT1r = 0.f;
    float itau = 1.f;
    if (tid < 128) {
        itau = 1.0f / sTa[row];
        h0r = h0[(size_t)q * Hdim + jrow + row];
        h1r = h0[(size_t)(q + 8) * Hdim + jrow + row];
        hT0r = my_tanh(h0r);
        hT1r = my_tanh(h1r);
        __stcg(&g_v[0][0][q * Hdim + jrow + row], hT0r);
        __stcg(&g_v[1][0][q * Hdim + jrow + row], hT1r);
        sHT0[row * 8 + q] = hT0r;
        sHT1[row * 8 + q] = hT1r;
    }
    __syncthreads();
    if (zf && tid < 128) {
        int bb = tid >> 3, oo = tid & 7;
        const float* ht = (bb < 8) ? sHT0 : sHT1;
        int bl = bb & 7;
        float s = 0.f;
#pragma unroll
        for (int j2 = 0; j2 < RPC; j2++) s = fmaf(ht[j2 * 8 + bl], sWo[oo * 16 + j2], s);
        __stcg(&g_zp0[cta * 128 + tid], s);
    }
    __syncthreads();
    if (tid == 0) {
        red_release(&g_wcnt[0][myg * PAD]);
        red_release(&g_wcnt[1][myg * PAD]);
        if (zf) red_release(&g_zcnt[0]);
    }

    unsigned tgt0 = 32u, tgt1 = 32u;
    bool f0_1 = false, f0_2 = false, f0_3 = false;
    bool f1_1 = false, f1_2 = false, f1_3 = false;

    // ---- prologue: half0 step0 head: own poll, snapshot, pf c0,c1 ----
    if (l == 0) {
        while (ldrelax(pc0[0]) < tgt0) {}
        while (ldacq(pc0[0]) < tgt0) {}
        f0_1 = (ldacq(pc0[1]) >= tgt0);
        f0_2 = (ldacq(pc0[2]) >= tgt0);
        f0_3 = (ldacq(pc0[3]) >= tgt0);
    }
    __syncwarp();
    pf_half(sV, g_v[0][0], 0, ci0, tid);
    wpoll(f0_1, pc0[1], tgt0, l);
    pf_half(sV, g_v[0][0], 1, ci1, tid);

    // ---- time loop ----
    for (int t = 0; t < Tdim; t++) {
        const int cb = t & 1, nb = cb ^ 1;

        // ================= PHASE 0 =================
        if (tid < 128)
            sX[tid] = x[((size_t)(tid >> 3) * Tdim + t) * NIN + (tid & 7)];
        if (zf) {
            if (tid == 0) {
                unsigned zt_ = 128u * (unsigned)(t + 1);
                while (ldrelax(&g_zcnt[0]) < zt_) {}
                while (ldacq(&g_zcnt[0]) < zt_) {}
            }
            __syncthreads();
            if (tid < 128) {
                const float* zp = (t == 0) ? (g_zp0 + tid)
                                           : (g_zt + (size_t)(t - 1) * (NCTA * 128) + tid);
                float s = 0.f;
#pragma unroll 8
                for (int c2 = 0; c2 < NCTA; c2++) s += __ldcg(zp + c2 * 128);
                sZ[tid] = s;
            }
        }
        // head for half1 (this step)
        if (l == 0) {
            while (ldrelax(pc1[0]) < tgt1) {}
            while (ldacq(pc1[0]) < tgt1) {}
            f1_1 = (ldacq(pc1[1]) >= tgt1);
            f1_2 = (ldacq(pc1[2]) >= tgt1);
            f1_3 = (ldacq(pc1[3]) >= tgt1);
        }
        __syncwarp();
        pf_half(sV, g_v[1][cb], 2, ci0, tid);

        {
            u64 acc[64];
#pragma unroll
            for (int i = 0; i < 64; i++) acc[i] = 0ull;
            // i0
            asm volatile("cp.async.wait_group 2;" ::: "memory");
            __syncthreads();
            wpoll(f1_1, pc1[1], tgt1, l);
            pf_half(sV, g_v[1][cb], 3, ci1, tid);
            cfma(sWm, sV, acc, rbase, kg, l, ci0, 0);
            // i1
            asm volatile("cp.async.wait_group 2;" ::: "memory");
            __syncthreads();
            wpoll(f0_2, pc0[2], tgt0, l);
            pf_half(sV, g_v[0][cb], 0, ci2, tid);
            cfma(sWm, sV, acc, rbase, kg, l, ci1, 1);
            // i2
            asm volatile("cp.async.wait_group 0;" ::: "memory");
            __syncthreads();
            wpoll(f0_3, pc0[3], tgt0, l);
            pf_half(sV, g_v[0][cb], 1, ci3, tid);
            cfma(sWm, sV, acc, rbase, kg, l, ci2, 0);
            // i3
            asm volatile("cp.async.wait_group 0;" ::: "memory");
            __syncthreads();
            cfma(sWm, sV, acc, rbase, kg, l, ci3, 1);

            // reduce
            float a[32];
#pragma unroll
            for (int i = 0; i < 32; i++) a[i] = unpack_sum(acc[i]);
            float recA = merge32(a, l);
#pragma unroll
            for (int i = 0; i < 32; i++) a[i] = unpack_sum(acc[32 + i]);
            float recB = merge32(a, l);
            int cellA = (rbase + (l >> 3)) * 8 + (l & 7);
            sP[kg * 128 + cellA] = recA;
            sP[kg * 128 + cellA + 32] = recB;
        }
        __syncthreads();
        // update half0
        if (tid < 128) {
            float rec = sP[tid] + sP[128 + tid] + sP[256 + tid] + sP[384 + tid];
            float inx = 0.f, zt = 0.f;
#pragma unroll
            for (int i = 0; i < NIN; i++) inx = fmaf(sX[q * 8 + i], sWi[row * 8 + i], inx);
            if (zf) {
#pragma unroll
                for (int o = 0; o < NOUT; o++) zt = fmaf(sZ[q * 8 + o], sWz[row * 8 + o], zt);
            }
            float rs = fmaf(-BETAC * r0r, hT0r, (1.0f - r0r) * itau);
            float rN = fmaf(rs, DTC, r0r);
            float s = rec + inx + zt - h0r;
            float hN = fmaf(s, 0.1f, h0r);
            float hTN = my_tanh(hN);
            __stcg(&g_v[0][nb][q * Hdim + jrow + row], rN * hTN);
            size_t oi = ((size_t)q * Tdim + t) * Hdim + jrow + row;
            stcs(&out_h[oi], hN);
            stcs(&out_r[oi], rN);
            sHT0[row * 8 + q] = hTN;
            h0r = hN; r0r = rN; hT0r = hTN;
        }
        __syncthreads();
        if (tid == 0) red_release(&g_wcnt[0][myg * PAD]);
        if (tid < 64) {
            int bl = tid >> 3, oo = tid & 7;
            float s = 0.f;
#pragma unroll
            for (int j2 = 0; j2 < RPC; j2++) s = fmaf(sHT0[j2 * 8 + bl], sWo[oo * 16 + j2], s);
            stcs(&g_zt[(size_t)t * (NCTA * 128) + cta * 128 + bl * 8 + oo], s);
        }
        tgt0 += 32u;

        // ================= PHASE 1 =================
        const bool hn = (t + 1 < Tdim);
        if (hn) {
            if (l == 0) {
                while (ldrelax(pc0[0]) < tgt0) {}
                while (ldacq(pc0[0]) < tgt0) {}
                f0_1 = (ldacq(pc0[1]) >= tgt0);
                f0_2 = (ldacq(pc0[2]) >= tgt0);
                f0_3 = (ldacq(pc0[3]) >= tgt0);
            }
            __syncwarp();
            pf_half(sV, g_v[0][nb], 0, ci0, tid);
        }
        {
            u64 acc[64];
#pragma unroll
            for (int i = 0; i < 64; i++) acc[i] = 0ull;
            // i0
            if (hn) { asm volatile("cp.async.wait_group 2;" ::: "memory"); }
            else    { asm volatile("cp.async.wait_group 1;" ::: "memory"); }
            __syncthreads();
            if (hn) {
                wpoll(f0_1, pc0[1], tgt0, l);
                pf_half(sV, g_v[0][nb], 1, ci1, tid);
            }
            cfma(sWm, sV, acc, rbase, kg, l, ci0, 2);
            // i1
            if (hn) { asm volatile("cp.async.wait_group 2;" ::: "memory"); }
            else    { asm volatile("cp.async.wait_group 1;" ::: "memory"); }
            __syncthreads();
            wpoll(f1_2, pc1[2], tgt1, l);
            pf_half(sV, g_v[1][cb], 2, ci2, tid);
            cfma(sWm, sV, acc, rbase, kg, l, ci1, 3);
            // i2
            asm volatile("cp.async.wait_group 0;" ::: "memory");
            __syncthreads();
            wpoll(f1_3, pc1[3], tgt1, l);
            pf_half(sV, g_v[1][cb], 3, ci3, tid);
            cfma(sWm, sV, acc, rbase, kg, l, ci2, 2);
            // i3
            asm volatile("cp.async.wait_group 0;" ::: "memory");
            __syncthreads();
            cfma(sWm, sV, acc, rbase, kg, l, ci3, 3);

            float a[32];
#pragma unroll
            for (int i = 0; i < 32; i++) a[i] = unpack_sum(acc[i]);
            float recA = merge32(a, l);
#pragma unroll
            for (int i = 0; i < 32; i++) a[i] = unpack_sum(acc[32 + i]);
            float recB = merge32(a, l);
            int cellA = (rbase + (l >> 3)) * 8 + (l & 7);
            sP[kg * 128 + cellA] = recA;
            sP[kg * 128 + cellA + 32] = recB;
        }
        __syncthreads();
        // update half1
        if (tid < 128) {
            float rec = sP[tid] + sP[128 + tid] + sP[256 + tid] + sP[384 + tid];
            float inx = 0.f, zt = 0.f;
#pragma unroll
            for (int i = 0; i < NIN; i++) inx = fmaf(sX[(q + 8) * 8 + i], sWi[row * 8 + i], inx);
            if (zf) {
#pragma unroll
                for (int o = 0; o < NOUT; o++) zt = fmaf(sZ[(q + 8) * 8 + o], sWz[row * 8 + o], zt);
            }
            float rs = fmaf(-BETAC * r1r, hT1r, (1.0f - r1r) * itau);
            float rN = fmaf(rs, DTC, r1r);
            float s = rec + inx + zt - h1r;
            float hN = fmaf(s, 0.1f, h1r);
            float hTN = my_tanh(hN);
            __stcg(&g_v[1][nb][q * Hdim + jrow + row], rN * hTN);
            size_t oi = ((size_t)(q + 8) * Tdim + t) * Hdim + jrow + row;
            stcs(&out_h[oi], hN);
            stcs(&out_r[oi], rN);
            sHT1[row * 8 + q] = hTN;
            h1r = hN; r1r = rN; hT1r = hTN;
        }
        __syncthreads();
        if (tid == 0) red_release(&g_wcnt[1][myg * PAD]);
        if (tid < 64) {
            int bl = tid >> 3, oo = tid & 7;
            float s = 0.f;
#pragma unroll
            for (int j2 = 0; j2 < RPC; j2++) s = fmaf(sHT1[j2 * 8 + bl], sWo[oo * 16 + j2], s);
            stcs(&g_zt[(size_t)t * (NCTA * 128) + cta * 128 + 64 + bl * 8 + oo], s);
        }
        if (zf) {
            __syncthreads();
            if (tid == 0) red_release(&g_zcnt[0]);
        }
        tgt1 += 32u;
    }
}

extern "C" void kernel_launch(void* const* d_in, const int* in_sizes, int n_in,
                              void* d_out, int out_size) {
    const float* x   = (const float*)d_in[0];
    const float* h0  = (const float*)d_in[1];
    const float* Wih = (const float*)d_in[2];
    const float* Wt  = (const float*)d_in[3];
    const float* Wf  = (const float*)d_in[4];
    const float* mk  = (const float*)d_in[5];
    const float* Whz = (const float*)d_in[6];
    const float* Wzh = (const float*)d_in[7];
    const float* tau = (const float*)d_in[8];
    float* out = (float*)d_out;

    reset_counters<<<1, 256>>>();
    scan_wzh<<<(Hdim * NOUT + 255) / 256, 256>>>(Wzh);
    build_wm<<<(Hdim * Hdim + 255) / 256, 256>>>(Wt, Wf, mk);

    cudaFuncSetAttribute(rnn_persist, cudaFuncAttributeMaxDynamicSharedMemorySize, 50576 * 4);
    rnn_persist<<<NCTA, NTH, 50576 * 4>>>(x, h0, Wih, Whz, Wzh, tau, out);

    zred<<<(Tdim * 128) / 256, 256>>>(out);
}